// round 9
// baseline (speedup 1.0000x reference)
#include <cuda_runtime.h>

// Locally-connected 3x3 conv, unshared weights:
// out[b,i,j] = 9 * sum_{m,n} x[b,i+m,j+n] * w[i,j,3m+n] + sum_k b[i,j,k]
// x zero-padded on the high side of both spatial dims.
//
// Block = 256 threads = jt(16 col-pairs) x ii(4 rows) x bq(4).
// Grid  = (8 col-tiles, 64 row-tiles of 4, 2 batch-halves) = 1024 blocks.
// 4-row tiles: block reads 6 x-rows for 4 output rows (1.5x halo amp,
// the best-measured traffic shape). Thread: 2 cols x 8 consecutive batches
// (b = bz*32 + bq*8 + bi). 32-bit indexing, reg cap 36 (launch_bounds 256,7)
// -> 7 blocks/SM -> all 1024 blocks co-resident: single wave, no tail.

#define Wd 256
#define Hd 256
#define IMG 65536u            // Wd*Hd, fits in 32-bit offsets

__global__ __launch_bounds__(256, 7)
void lc_kernel(const float* __restrict__ x,
               const float* __restrict__ w,
               const float* __restrict__ bvec,
               float* __restrict__ out) {
    __shared__ float ws[1152];   // [row*288 + col*9 + k], 4 rows x 32 cols x 9
    __shared__ float bs[1152];

    const int t  = threadIdx.x;
    const int jt = t & 15;          // 0..15 : column pair
    const int ii = (t >> 4) & 3;    // 0..3  : row within tile
    const int bq = t >> 6;          // 0..3  : batch quarter within half

    const int i0 = blockIdx.y * 4;
    const int j0 = blockIdx.x * 32;
    const int i  = i0 + ii;
    const int j  = j0 + jt * 2;

    // ---- stage w/b tile (coalesced), once per block ----
    #pragma unroll
    for (int idx = t; idx < 1152; idx += 256) {
        int r    = idx / 288;
        int rest = idx - r * 288;        // 32 cols * 9 units
        unsigned g = ((unsigned)(i0 + r) * Hd + j0) * 9u + rest;
        ws[idx] = w[g];
        bs[idx] = bvec[g];
    }
    __syncthreads();

    // ---- per-thread weights (2 cols x 9) + bias sums -> registers ----
    float wr[2][9];
    float bsum[2];
    {
        const int base = ii * 288 + jt * 18;
        #pragma unroll
        for (int c = 0; c < 2; c++) {
            float s = 0.f;
            #pragma unroll
            for (int k = 0; k < 9; k++) {
                wr[c][k] = ws[base + c * 9 + k];
                s += bs[base + c * 9 + k];
            }
            bsum[c] = s;
        }
    }

    const bool qok  = (j + 2 < Hd);
    const bool r1ok = (i + 1 < Wd);
    const bool r2ok = (i + 2 < Wd);
    const float2 z2 = make_float2(0.f, 0.f);

    // batches: b = bz*32 + bq*8 + bi, bi = 0..7 (consecutive walk)
    unsigned off = (blockIdx.z * 32u + (unsigned)bq * 8u) * IMG
                 + (unsigned)i * Hd + (unsigned)j;

    #pragma unroll 1
    for (int bi = 0; bi < 8; bi++) {
        const float* xb = x + off;

        float2 p0, q0, p1, q1, p2, q2;
        p0 = *(const float2*)xb;
        q0 = qok ? *(const float2*)(xb + 2) : z2;
        if (r1ok) {
            p1 = *(const float2*)(xb + Hd);
            q1 = qok ? *(const float2*)(xb + Hd + 2) : z2;
        } else { p1 = z2; q1 = z2; }
        if (r2ok) {
            p2 = *(const float2*)(xb + 2 * Hd);
            q2 = qok ? *(const float2*)(xb + 2 * Hd + 2) : z2;
        } else { p2 = z2; q2 = z2; }

        float a0 = p0.x * wr[0][0];
        a0 = fmaf(p0.y, wr[0][1], a0);
        a0 = fmaf(q0.x, wr[0][2], a0);
        a0 = fmaf(p1.x, wr[0][3], a0);
        a0 = fmaf(p1.y, wr[0][4], a0);
        a0 = fmaf(q1.x, wr[0][5], a0);
        a0 = fmaf(p2.x, wr[0][6], a0);
        a0 = fmaf(p2.y, wr[0][7], a0);
        a0 = fmaf(q2.x, wr[0][8], a0);

        float a1 = p0.y * wr[1][0];
        a1 = fmaf(q0.x, wr[1][1], a1);
        a1 = fmaf(q0.y, wr[1][2], a1);
        a1 = fmaf(p1.y, wr[1][3], a1);
        a1 = fmaf(q1.x, wr[1][4], a1);
        a1 = fmaf(q1.y, wr[1][5], a1);
        a1 = fmaf(p2.y, wr[1][6], a1);
        a1 = fmaf(q2.x, wr[1][7], a1);
        a1 = fmaf(q2.y, wr[1][8], a1);

        *(float2*)(out + off) = make_float2(fmaf(9.f, a0, bsum[0]),
                                            fmaf(9.f, a1, bsum[1]));
        off += IMG;
    }
}

extern "C" void kernel_launch(void* const* d_in, const int* in_sizes, int n_in,
                              void* d_out, int out_size) {
    const float* x   = (const float*)d_in[0];
    const float* w   = (const float*)d_in[1];
    const float* b   = (const float*)d_in[2];
    float*       out = (float*)d_out;

    dim3 grid(8, 64, 2);   // (col-tiles of 32, row-tiles of 4, batch halves)
    lc_kernel<<<grid, 256>>>(x, w, b, out);
}

// round 11
// speedup vs baseline: 1.4571x; 1.4571x over previous
#include <cuda_runtime.h>

// Locally-connected 3x3 conv, unshared weights:
// out[b,i,j] = 9 * sum_{m,n} x[b,i+m,j+n] * w[i,j,3m+n] + sum_k b[i,j,k]
// x zero-padded on the high side of both spatial dims.
//
// R2 structure (measured best): Block = 256 threads = jt(16 col-pairs) x
// ii(4 rows) x bq(4). Grid = (8 col-tiles, 64 row-tiles) = 512 blocks,
// 5 blocks/SM -> capacity 740 >= 512: all blocks co-resident, no tail.
// Each thread: 2 cols x 16 batches. Weight tile staged once (1x traffic).
// Changes vs R2: unroll 4 (double in-flight loads, ~24 MLP) + 32-bit offsets.

#define Wd 256
#define Hd 256
#define IMG 65536u            // Wd*Hd, fits in 32-bit offsets

__global__ __launch_bounds__(256, 5)
void lc_kernel(const float* __restrict__ x,
               const float* __restrict__ w,
               const float* __restrict__ bvec,
               float* __restrict__ out) {
    __shared__ float ws[1152];   // [row*288 + col*9 + k], 4 rows x 32 cols x 9
    __shared__ float bs[1152];

    const int t  = threadIdx.x;
    const int jt = t & 15;          // 0..15 : column pair
    const int ii = (t >> 4) & 3;    // 0..3  : row within tile
    const int bq = t >> 6;          // 0..3  : batch quarter

    const int i0 = blockIdx.y * 4;
    const int j0 = blockIdx.x * 32;
    const int i  = i0 + ii;
    const int j  = j0 + jt * 2;

    // ---- stage w/b tile (coalesced), once per block; tiles disjoint ----
    #pragma unroll
    for (int idx = t; idx < 1152; idx += 256) {
        int r    = idx / 288;
        int rest = idx - r * 288;        // 32 cols * 9 units
        unsigned g = ((unsigned)(i0 + r) * Hd + j0) * 9u + rest;
        ws[idx] = w[g];
        bs[idx] = bvec[g];
    }
    __syncthreads();

    // ---- per-thread weights (2 cols x 9) + bias sums -> registers ----
    float wr[2][9];
    float bsum[2];
    {
        const int base = ii * 288 + jt * 18;
        #pragma unroll
        for (int c = 0; c < 2; c++) {
            float s = 0.f;
            #pragma unroll
            for (int k = 0; k < 9; k++) {
                wr[c][k] = ws[base + c * 9 + k];
                s += bs[base + c * 9 + k];
            }
            bsum[c] = s;
        }
    }

    const bool qok  = (j + 2 < Hd);
    const bool r1ok = (i + 1 < Wd);
    const bool r2ok = (i + 2 < Wd);
    const float2 z2 = make_float2(0.f, 0.f);

    // batches: b = bq*16 + bi, bi = 0..15 (consecutive walk)
    unsigned off = (unsigned)(bq * 16) * IMG + (unsigned)i * Hd + (unsigned)j;

    #pragma unroll 4
    for (int bi = 0; bi < 16; bi++) {
        const float* xb = x + off;

        float2 p0, q0, p1, q1, p2, q2;
        p0 = *(const float2*)xb;
        q0 = qok ? *(const float2*)(xb + 2) : z2;
        if (r1ok) {
            p1 = *(const float2*)(xb + Hd);
            q1 = qok ? *(const float2*)(xb + Hd + 2) : z2;
        } else { p1 = z2; q1 = z2; }
        if (r2ok) {
            p2 = *(const float2*)(xb + 2 * Hd);
            q2 = qok ? *(const float2*)(xb + 2 * Hd + 2) : z2;
        } else { p2 = z2; q2 = z2; }

        float a0 = p0.x * wr[0][0];
        a0 = fmaf(p0.y, wr[0][1], a0);
        a0 = fmaf(q0.x, wr[0][2], a0);
        a0 = fmaf(p1.x, wr[0][3], a0);
        a0 = fmaf(p1.y, wr[0][4], a0);
        a0 = fmaf(q1.x, wr[0][5], a0);
        a0 = fmaf(p2.x, wr[0][6], a0);
        a0 = fmaf(p2.y, wr[0][7], a0);
        a0 = fmaf(q2.x, wr[0][8], a0);

        float a1 = p0.y * wr[1][0];
        a1 = fmaf(q0.x, wr[1][1], a1);
        a1 = fmaf(q0.y, wr[1][2], a1);
        a1 = fmaf(p1.y, wr[1][3], a1);
        a1 = fmaf(q1.x, wr[1][4], a1);
        a1 = fmaf(q1.y, wr[1][5], a1);
        a1 = fmaf(p2.y, wr[1][6], a1);
        a1 = fmaf(q2.x, wr[1][7], a1);
        a1 = fmaf(q2.y, wr[1][8], a1);

        *(float2*)(out + off) = make_float2(fmaf(9.f, a0, bsum[0]),
                                            fmaf(9.f, a1, bsum[1]));
        off += IMG;
    }
}

extern "C" void kernel_launch(void* const* d_in, const int* in_sizes, int n_in,
                              void* d_out, int out_size) {
    const float* x   = (const float*)d_in[0];
    const float* w   = (const float*)d_in[1];
    const float* b   = (const float*)d_in[2];
    float*       out = (float*)d_out;

    dim3 grid(8, 64);   // (col-tiles of 32, row-tiles of 4)
    lc_kernel<<<grid, 256>>>(x, w, b, out);
}